// round 1
// baseline (speedup 1.0000x reference)
#include <cuda_runtime.h>
#include <cstdint>
#include <math.h>

#define NLEV 16

struct LevelMeta {
    float    scale;   // np.float32(16*exp(i*log(s)) - 1)
    uint32_t res;     // encode resolution = ceil(f32 scale)+1
    uint32_t res2;    // res*res
    uint32_t size;    // padded, capped map size (entries)
    uint32_t offset;  // cumulative offset in entries (float2 units)
    uint32_t hashed;  // 1 => hash path, 0 => dense path
    uint32_t pad0, pad1;
};

__device__ LevelMeta g_meta[NLEV];

// Computes level metadata exactly as the numpy reference (fp64), on device,
// so no host->device memcpy is needed inside graph capture.
__global__ void setup_meta_kernel() {
    if (threadIdx.x != 0 || blockIdx.x != 0) return;
    const double s  = 1.3195079565048218;
    const double ls = log(s);
    uint64_t off = 0;
    for (int i = 0; i < NLEV; ++i) {
        double  t       = exp((double)i * ls);
        double  scale_d = 16.0 * t - 1.0;
        float   scale_f = (float)scale_d;
        uint32_t res_meta = (uint32_t)ceil(scale_d) + 1u;   // _level_meta: f64 ceil
        uint32_t res_enc  = (uint32_t)ceilf(scale_f) + 1u;  // _encode: f32 ceil
        uint64_t p = (uint64_t)res_meta * res_meta * res_meta;
        if (p % 8ull) p = ((p + 7ull) / 8ull) * 8ull;
        uint64_t sz = p < 524288ull ? p : 524288ull;        // min(MAX_PARAMS, p)
        uint32_t indicator =
            ((uint64_t)res_meta * res_meta * res_meta <= sz) ? 1u : 0u;
        LevelMeta m;
        m.scale  = scale_f;
        m.res    = res_enc;
        m.res2   = res_enc * res_enc;
        m.size   = (uint32_t)sz;
        m.offset = (uint32_t)off;
        m.hashed = indicator ? 0u : 1u;
        m.pad0 = 0; m.pad1 = 0;
        g_meta[i] = m;
        off += sz;
    }
}

// Block: 32 points x 16 levels (512 threads).
// warp = 32 consecutive points at one level (uniform dense/hash branch).
__global__ __launch_bounds__(512)
void hashenc_kernel(const float* __restrict__ positions,
                    const float* __restrict__ table,
                    float*       __restrict__ out,
                    int B)
{
    __shared__ float  sp[96];          // 32 points * xyz
    __shared__ float2 sout[32][17];    // [point][level], padded vs bank conflicts

    const int b0  = blockIdx.x << 5;
    const int tid = threadIdx.x;

    if (tid < 96) {
        long long gi = (long long)b0 * 3 + tid;
        sp[tid] = (gi < (long long)B * 3) ? positions[gi] : 0.0f;
    }
    __syncthreads();

    const int x   = tid & 31;   // point within block
    const int lev = tid >> 5;   // level (uniform per warp)

    const LevelMeta m = g_meta[lev];

    const float px = sp[x * 3 + 0];
    const float py = sp[x * 3 + 1];
    const float pz = sp[x * 3 + 2];

    // pos*scale + 0.5 with NO fma contraction (match XLA mul-then-add)
    const float qx = __fadd_rn(__fmul_rn(px, m.scale), 0.5f);
    const float qy = __fadd_rn(__fmul_rn(py, m.scale), 0.5f);
    const float qz = __fadd_rn(__fmul_rn(pz, m.scale), 0.5f);

    const float flx = floorf(qx), fly = floorf(qy), flz = floorf(qz);
    const float fx = __fsub_rn(qx, flx);
    const float fy = __fsub_rn(qy, fly);
    const float fz = __fsub_rn(qz, flz);
    const uint32_t gx = (uint32_t)(int)flx;
    const uint32_t gy = (uint32_t)(int)fly;
    const uint32_t gz = (uint32_t)(int)flz;

    const float wx0 = 1.0f - fx, wx1 = fx;
    const float wy0 = 1.0f - fy, wy1 = fy;
    const float wz0 = 1.0f - fz, wz1 = fz;

    uint32_t idxs[8];
    if (m.hashed) {
        const uint32_t mask = m.size - 1u;   // hashed levels: size == 2^19
        const uint32_t hx0 = gx;
        const uint32_t hx1 = gx + 1u;
        const uint32_t hy0 = gy        * 2654435761u;
        const uint32_t hy1 = (gy + 1u) * 2654435761u;
        const uint32_t hz0 = gz        * 805459861u;
        const uint32_t hz1 = (gz + 1u) * 805459861u;
        idxs[0] = (hx0 ^ hy0 ^ hz0) & mask;
        idxs[1] = (hx1 ^ hy0 ^ hz0) & mask;
        idxs[2] = (hx0 ^ hy1 ^ hz0) & mask;
        idxs[3] = (hx1 ^ hy1 ^ hz0) & mask;
        idxs[4] = (hx0 ^ hy0 ^ hz1) & mask;
        idxs[5] = (hx1 ^ hy0 ^ hz1) & mask;
        idxs[6] = (hx0 ^ hy1 ^ hz1) & mask;
        idxs[7] = (hx1 ^ hy1 ^ hz1) & mask;
    } else {
        // dense: h = x + y*res + z*res^2, then h % size with h < 2*size
        const uint32_t cx0 = gx;
        const uint32_t cx1 = gx + 1u;
        const uint32_t cy0 = gy        * m.res;
        const uint32_t cy1 = (gy + 1u) * m.res;
        const uint32_t cz0 = gz        * m.res2;
        const uint32_t cz1 = (gz + 1u) * m.res2;
        const uint32_t sz  = m.size;
        uint32_t h;
        h = cx0 + cy0 + cz0; idxs[0] = h - (h >= sz ? sz : 0u);
        h = cx1 + cy0 + cz0; idxs[1] = h - (h >= sz ? sz : 0u);
        h = cx0 + cy1 + cz0; idxs[2] = h - (h >= sz ? sz : 0u);
        h = cx1 + cy1 + cz0; idxs[3] = h - (h >= sz ? sz : 0u);
        h = cx0 + cy0 + cz1; idxs[4] = h - (h >= sz ? sz : 0u);
        h = cx1 + cy0 + cz1; idxs[5] = h - (h >= sz ? sz : 0u);
        h = cx0 + cy1 + cz1; idxs[6] = h - (h >= sz ? sz : 0u);
        h = cx1 + cy1 + cz1; idxs[7] = h - (h >= sz ? sz : 0u);
    }

    const float2* __restrict__ t2 =
        reinterpret_cast<const float2*>(table) + m.offset;

    float acc0 = 0.0f, acc1 = 0.0f;
    {
        const float2 f0 = __ldg(&t2[idxs[0]]);
        const float2 f1 = __ldg(&t2[idxs[1]]);
        const float2 f2 = __ldg(&t2[idxs[2]]);
        const float2 f3 = __ldg(&t2[idxs[3]]);
        const float2 f4 = __ldg(&t2[idxs[4]]);
        const float2 f5 = __ldg(&t2[idxs[5]]);
        const float2 f6 = __ldg(&t2[idxs[6]]);
        const float2 f7 = __ldg(&t2[idxs[7]]);

        const float w0 = wx0 * wy0 * wz0;
        const float w1 = wx1 * wy0 * wz0;
        const float w2 = wx0 * wy1 * wz0;
        const float w3 = wx1 * wy1 * wz0;
        const float w4 = wx0 * wy0 * wz1;
        const float w5 = wx1 * wy0 * wz1;
        const float w6 = wx0 * wy1 * wz1;
        const float w7 = wx1 * wy1 * wz1;

        acc0 = fmaf(w0, f0.x, acc0); acc1 = fmaf(w0, f0.y, acc1);
        acc0 = fmaf(w1, f1.x, acc0); acc1 = fmaf(w1, f1.y, acc1);
        acc0 = fmaf(w2, f2.x, acc0); acc1 = fmaf(w2, f2.y, acc1);
        acc0 = fmaf(w3, f3.x, acc0); acc1 = fmaf(w3, f3.y, acc1);
        acc0 = fmaf(w4, f4.x, acc0); acc1 = fmaf(w4, f4.y, acc1);
        acc0 = fmaf(w5, f5.x, acc0); acc1 = fmaf(w5, f5.y, acc1);
        acc0 = fmaf(w6, f6.x, acc0); acc1 = fmaf(w6, f6.y, acc1);
        acc0 = fmaf(w7, f7.x, acc0); acc1 = fmaf(w7, f7.y, acc1);
    }

    sout[x][lev] = make_float2(acc0, acc1);
    __syncthreads();

    // Coalesced write: 512 float2 = 32 points x 16 float2, contiguous 4KB.
    const int p = tid >> 4;
    const int l = tid & 15;
    if (b0 + p < B) {
        reinterpret_cast<float2*>(out)[(size_t)b0 * 16 + tid] = sout[p][l];
    }
}

extern "C" void kernel_launch(void* const* d_in, const int* in_sizes, int n_in,
                              void* d_out, int out_size) {
    const float* positions = (const float*)d_in[0];
    const float* table     = (const float*)d_in[1];
    float*       out       = (float*)d_out;
    const int B = in_sizes[0] / 3;

    setup_meta_kernel<<<1, 1>>>();
    const int nblocks = (B + 31) / 32;
    hashenc_kernel<<<nblocks, 512>>>(positions, table, out, B);
}